// round 15
// baseline (speedup 1.0000x reference)
#include <cuda_runtime.h>
#include <cuda_fp16.h>
#include <cstdint>

#define NB    8
#define PPC   1024
#define NPTS  8192
#define KNN   20
#define NEDGE (NPTS*KNN)

// ---------------- scratch (device globals; allocation-free) ----------------
__device__ int   g_nbr[NEDGE];
__device__ __align__(16) float g_h1T[64*NEDGE];    // layer1 out, TRANSPOSED [c][edge]
__device__ __align__(16) unsigned g_x1m[128*NPTS]; // max-aggregated, mono-encoded [c][n]
__device__ __align__(16) unsigned g_xgM[NB*1024];  // pooled max (mono)
__device__ __align__(16) float    g_xgS[NB*1024];  // pooled sum
__device__ __align__(16) float g_Bp4[38400*40];    // layer4 coeffs [f][o]
__device__ __align__(16) __half g_B1h[64*104];     // layer1 coeffs hi
__device__ __align__(16) __half g_B1l[64*104];     // lo
__device__ __align__(16) __half g_B2[128*1120];    // layer2 coeffs, frag-permuted
__device__ __align__(16) __half g_B3[1024*2240];   // layer3 coeffs, frag-permuted
__device__ float g_l4p[NB*8*40];

// ---------------- small helpers ----------------
__device__ __forceinline__ uint32_t pack_h2(float lo, float hi) {
    __half2 h = __floats2half2_rn(lo, hi);
    return *(uint32_t*)&h;
}
__device__ __forceinline__ void mma_f16(float* c, const uint32_t* a,
                                        uint32_t b0, uint32_t b1) {
    asm volatile(
        "mma.sync.aligned.m16n8k16.row.col.f32.f16.f16.f32 "
        "{%0,%1,%2,%3}, {%4,%5,%6,%7}, {%8,%9}, {%0,%1,%2,%3};\n"
        : "+f"(c[0]), "+f"(c[1]), "+f"(c[2]), "+f"(c[3])
        : "r"(a[0]), "r"(a[1]), "r"(a[2]), "r"(a[3]), "r"(b0), "r"(b1));
}
__device__ __forceinline__ void cp16(uint32_t dst, const void* src) {
    asm volatile("cp.async.cg.shared.global [%0], [%1], 16;" :: "r"(dst), "l"(src));
}
#define CP_COMMIT() asm volatile("cp.async.commit_group;" ::: "memory")
#define CP_WAIT0()  asm volatile("cp.async.wait_group 0;" ::: "memory")

// monotonic float <-> uint mapping (order-preserving under unsigned compare)
__device__ __forceinline__ unsigned fmono(float x) {
    unsigned u = __float_as_uint(x);
    return ((int)u >= 0) ? (u | 0x80000000u) : ~u;
}
__device__ __forceinline__ float fmono_inv(unsigned m) {
    return (m & 0x80000000u) ? __uint_as_float(m & 0x7fffffffu)
                             : __uint_as_float(~m);
}
#define MONO_NEG_INF 0x007fffffu

// frag permutation: kpos within 80-k chunk -> physical half, with row XOR swizzle
__device__ __forceinline__ int bperm(int kp, int row) {
    int frag = kp >> 4, k16 = kp & 15;
    int u = 2 * ((k16 & 7) >> 1) + (k16 >> 3);
    int g = 2 * ((row >> 2) & 3);
    return frag * 16 + (((u ^ g) << 1) | (k16 & 1));
}

// ---------------- packing kernels ----------------
// pack12: layer1 B (hi/lo) + layer2 B (fp16, frag-permuted) + init g_x1m
__global__ void pack12(const float* __restrict__ c1, const float* __restrict__ c2) {
    int idx = blockIdx.x * 256 + threadIdx.x;
    if (idx < 64 * 104) {
        int o = idx / 104, jj = idx - o * 104;
        float v = 0.f;
        if (jj < 96) {
            int c = jj >> 4, j = jj & 15;
            if (j < 10) {
                int trig = j & 1, k = j >> 1, w = c / 3, i = c % 3;
                v = c1[(((trig * 64 + o) * 2 + w) * 3 + i) * 5 + k];
            }
        }
        __half h = __float2half_rn(v);
        g_B1h[idx] = h;
        g_B1l[idx] = __float2half_rn(v - __half2float(h));
    } else if (idx < 64 * 104 + 128 * 1120) {
        int id2 = idx - 64 * 104;
        int k = id2 % 5, r1 = id2 / 5;
        int i = r1 % 16, r2 = r1 / 16;
        int w = r2 % 7, r3 = r2 / 7;
        int o = r3 % 128, trig = r3 / 128;
        int f = ((w * 16 + i) * 5 + k) * 2 + trig;
        int chunk = f / 80, kp = f - chunk * 80;
        g_B2[o * 1120 + chunk * 80 + bperm(kp, o)] = __float2half_rn(c2[id2]);
    } else {
        int id3 = idx - (64 * 104 + 128 * 1120);
        if (id3 < 128 * NPTS) g_x1m[id3] = MONO_NEG_INF;
    }
}

// pack3: layer3 B (frag-permuted) + init pooled accumulators
__global__ void pack3(const float* __restrict__ c3) {
    int idx = blockIdx.x * 256 + threadIdx.x;
    if (idx < 1024 * 2240) {
        int k = idx % 5, r1 = idx / 5;
        int i = r1 % 32, r2 = r1 / 32;
        int w = r2 % 7, r3 = r2 / 7;
        int o = r3 % 1024, trig = r3 / 1024;
        int f = ((w * 32 + i) * 5 + k) * 2 + trig;
        int chunk = f / 80, kp = f - chunk * 80;
        g_B3[(size_t)o * 2240 + chunk * 80 + bperm(kp, o)] = __float2half_rn(c3[idx]);
    } else {
        int j = idx - 1024 * 2240;
        if (j < NB * 1024) g_xgM[j] = MONO_NEG_INF;
        else if (j < 2 * NB * 1024) g_xgS[j - NB * 1024] = 0.f;
    }
}

__global__ void pack_coef4(const float* __restrict__ src) {
    int idx = blockIdx.x * 256 + threadIdx.x;
    if (idx >= 38400 * 40) return;
    int k = idx % 5, r1 = idx / 5;
    int i = r1 % 256, r2 = r1 / 256;
    int w = r2 % 15, r3 = r2 / 15;
    int o = r3 % 40, trig = r3 / 40;
    int f = ((w * 256 + i) * 5 + k) * 2 + trig;
    g_Bp4[(size_t)f * 40 + o] = src[idx];
}

// ---------------- kNN: register top-20 per query thread ----------------
__global__ void knn_kernel(const float* __restrict__ pos) {
    __shared__ float sx[PPC], sy[PPC], sz[PPC];
    int tid = threadIdx.x;
    int b   = blockIdx.x >> 2;
    int ql  = ((blockIdx.x & 3) << 8) + tid;
    for (int p = tid; p < PPC; p += 256) {
        const float* pp = pos + (b * PPC + p) * 3;
        sx[p] = pp[0]; sy[p] = pp[1]; sz[p] = pp[2];
    }
    __syncthreads();
    float qx = sx[ql], qy = sy[ql], qz = sz[ql];
    float v[KNN]; int id[KNN];
#pragma unroll
    for (int j = 0; j < KNN; ++j) { v[j] = 1e30f; id[j] = -1; }
    float vmax = 1e30f; int mpos = 0;
    for (int p = 0; p < PPC; ++p) {
        float dx = sx[p] - qx, dy = sy[p] - qy, dz = sz[p] - qz;
        float d = dx * dx + dy * dy + dz * dz;
        if (p == ql) d = 1e30f;
        if (d < vmax) {
#pragma unroll
            for (int j = 0; j < KNN; ++j) if (j == mpos) { v[j] = d; id[j] = p; }
            vmax = v[0]; mpos = 0;
#pragma unroll
            for (int j = 1; j < KNN; ++j) if (v[j] > vmax) { vmax = v[j]; mpos = j; }
        }
    }
    int q = b * PPC + ql;
#pragma unroll
    for (int j = 0; j < KNN; ++j) g_nbr[q * KNN + j] = b * PPC + id[j];
}

// ---------------- layer1 as fused-basis HMMA (fp16x3), M=128/block -----------
__global__ void __launch_bounds__(256, 2)
layer1_mma(const float* __restrict__ pos, const float* __restrict__ b1) {
    constexpr int SA1 = 104;
    extern __shared__ unsigned char smem[];
    __half* sAh = (__half*)smem;
    __half* sAl = (__half*)(smem + 26624);
    __half* sBh = (__half*)(smem + 53248);
    __half* sBl = (__half*)(smem + 66560);
    float*  bs  = (float*)(smem + 79872);
    float*  tr  = (float*)smem;

    int tid = threadIdx.x, lane = tid & 31, warp = tid >> 5;
    int wm = warp & 3, wn = warp >> 2;
    int qr = lane >> 2, qk = lane & 3;
    int row = tid & 127, cg = tid >> 7;

    if (tid >= 128) {
        int tt = tid - 128, str = tt >> 6, r = tt & 63;
        const uint4* src = (const uint4*)((str ? g_B1l : g_B1h) + r * 104);
        uint4* dst = (uint4*)((str ? sBl : sBh) + r * 104);
#pragma unroll
        for (int q = 0; q < 13; ++q) dst[q] = src[q];
    }
    if (tid < 64) bs[tid] = b1[tid];

    int edge = blockIdx.x * 128 + row;
    int n = edge / KNN;
    int pj = g_nbr[edge];
    float e[6];
    {
        const float* Pi = pos + n * 3;
        const float* Pj = pos + pj * 3;
        e[0] = Pi[0]; e[1] = Pi[1]; e[2] = Pi[2];
        e[3] = Pj[0] - Pi[0]; e[4] = Pj[1] - Pi[1]; e[5] = Pj[2] - Pi[2];
    }
#pragma unroll
    for (int cc = 0; cc < 3; ++cc) {
        int cl = cg * 3 + cc;
        int i = cl % 3;
        float ham = (i == 1) ? 1.0f : 0.08f;
        float a = e[cl] * ham;
        float s, c; __sincosf(a, &s, &c);
        uint32_t* ph = (uint32_t*)&sAh[row * SA1 + cl * 16];
        uint32_t* pl = (uint32_t*)&sAl[row * SA1 + cl * 16];
        float ck = c, sk = s;
#pragma unroll
        for (int k = 0; k < 5; ++k) {
            if (k) { float cn = ck * c - sk * s, sn = sk * c + ck * s; ck = cn; sk = sn; }
            __half chh = __float2half_rn(ck), shh = __float2half_rn(sk);
            ph[k] = pack_h2(ck, sk);
            pl[k] = pack_h2(ck - __half2float(chh), sk - __half2float(shh));
        }
        ph[5] = ph[6] = ph[7] = 0u;
        pl[5] = pl[6] = pl[7] = 0u;
    }
    __syncthreads();

    float acc[2][4][4];
#pragma unroll
    for (int m = 0; m < 2; ++m)
#pragma unroll
        for (int nf = 0; nf < 4; ++nf)
#pragma unroll
            for (int q = 0; q < 4; ++q) acc[m][nf][q] = 0.f;

#pragma unroll
    for (int ks = 0; ks < 6; ++ks) {
        int kb = ks * 16;
        uint32_t ah[2][4], al[2][4];
#pragma unroll
        for (int m = 0; m < 2; ++m) {
            int rb = (wm * 32 + m * 16 + qr) * SA1 + kb + qk * 2;
            ah[m][0] = *(const uint32_t*)&sAh[rb];
            ah[m][1] = *(const uint32_t*)&sAh[rb + 8 * SA1];
            ah[m][2] = *(const uint32_t*)&sAh[rb + 8];
            ah[m][3] = *(const uint32_t*)&sAh[rb + 8 * SA1 + 8];
            al[m][0] = *(const uint32_t*)&sAl[rb];
            al[m][1] = *(const uint32_t*)&sAl[rb + 8 * SA1];
            al[m][2] = *(const uint32_t*)&sAl[rb + 8];
            al[m][3] = *(const uint32_t*)&sAl[rb + 8 * SA1 + 8];
        }
#pragma unroll
        for (int nf = 0; nf < 4; ++nf) {
            int bb = (wn * 32 + nf * 8 + qr) * SA1 + kb + qk * 2;
            uint32_t bh0 = *(const uint32_t*)&sBh[bb];
            uint32_t bh1 = *(const uint32_t*)&sBh[bb + 8];
            uint32_t bl0 = *(const uint32_t*)&sBl[bb];
            uint32_t bl1 = *(const uint32_t*)&sBl[bb + 8];
#pragma unroll
            for (int m = 0; m < 2; ++m) {
                mma_f16(acc[m][nf], ah[m], bh0, bh1);
                mma_f16(acc[m][nf], al[m], bh0, bh1);
                mma_f16(acc[m][nf], ah[m], bl0, bl1);
            }
        }
    }
    __syncthreads();

#pragma unroll
    for (int m = 0; m < 2; ++m) {
        int r0 = wm * 32 + m * 16 + qr;
#pragma unroll
        for (int nf = 0; nf < 4; ++nf) {
            int c0 = wn * 32 + nf * 8 + qk * 2;
            tr[c0 * 132 + r0]           = acc[m][nf][0];
            tr[(c0 + 1) * 132 + r0]     = acc[m][nf][1];
            tr[c0 * 132 + r0 + 8]       = acc[m][nf][2];
            tr[(c0 + 1) * 132 + r0 + 8] = acc[m][nf][3];
        }
    }
    __syncthreads();
    int e0 = blockIdx.x * 128;
    for (int idx = tid; idx < 64 * 128; idx += 256) {
        int o = idx >> 7, r = idx & 127;
        g_h1T[(size_t)o * NEDGE + e0 + r] = tr[o * 132 + r] + bs[o];
    }
}

// ---------------- fp16x2 fused-basis GEMM, LDS.64 permuted layout -----------
// LAYER==2: 256 thr, tile 128x128; fused K-neighbor max epilogue
// LAYER==3: 512 thr, tile 128x256; fused global max+mean pooling epilogue
template<int LAYER>
__global__ void __launch_bounds__((LAYER == 2) ? 256 : 512, (LAYER == 2) ? 2 : 1)
kan_mma(const float* __restrict__ bias) {
    constexpr int W    = (LAYER == 2) ? 16 : 32;
    constexpr int S    = (LAYER == 2) ? 8  : 16;
    constexpr int M    = (LAYER == 2) ? NEDGE : NPTS;
    constexpr int NCH  = (LAYER == 2) ? 14 : 28;
    constexpr int KTOT = (LAYER == 2) ? 1120 : 2240;
    constexpr int NT   = (LAYER == 2) ? 128 : 256;   // n-cols per block
    constexpr int PC   = (LAYER == 2) ? 4 : 2;       // producer cols/thread
    constexpr uint32_t ABY = 128u * 80 * 2;           // 20480 per A stream
    constexpr uint32_t BBY = (uint32_t)NT * 160;      // 20480 / 40960

    extern __shared__ unsigned char dynsm[];
    uint32_t* sAh_w = (uint32_t*)dynsm;               // 5120 words
    uint32_t* sAl_w = sAh_w + 5120;
    uint32_t smem_b = (uint32_t)__cvta_generic_to_shared(dynsm);

    const unsigned* xsrc = (LAYER == 2) ? (const unsigned*)g_h1T : g_x1m;
    const __half* Bg = (LAYER == 2) ? g_B2 : g_B3;

    int m0 = blockIdx.x * 128;
    int n0 = blockIdx.y * NT;
    int tid = threadIdx.x;
    int lane = tid & 31, warp = tid >> 5;
    int wm = warp & 3, wn = warp >> 2;   // warp tile: 32 rows x 64 cols
    int qr = lane >> 2, qk = lane & 3;
    int row = tid & 127, cg = tid >> 7;  // producer mapping
    int gprod = 2 * ((row >> 2) & 3);    // producer row swizzle

    // fragment word-base indices (permuted layout, row stride 40 words)
    int aw[2][2], bw[8];
#pragma unroll
    for (int m = 0; m < 2; ++m) {
        int r0 = wm * 32 + m * 16 + qr, r1 = r0 + 8;
        aw[m][0] = r0 * 40 + ((2 * qk) ^ (2 * ((r0 >> 2) & 3)));
        aw[m][1] = r1 * 40 + ((2 * qk) ^ (2 * ((r1 >> 2) & 3)));
    }
#pragma unroll
    for (int nn = 0; nn < 8; ++nn) {
        int br = wn * 64 + nn * 8 + qr;
        bw[nn] = br * 40 + ((2 * qk) ^ (2 * ((br >> 2) & 3)));
    }

    float acc[2][8][4];
#pragma unroll
    for (int m = 0; m < 2; ++m)
#pragma unroll
        for (int nn = 0; nn < 8; ++nn)
#pragma unroll
            for (int q = 0; q < 4; ++q) acc[m][nn][q] = 0.f;

    unsigned xv[PC], xn[PC];

    auto ldx = [&](int ch, unsigned* d) {
#pragma unroll
        for (int cc = 0; cc < PC; ++cc) {
            int cl = cg * PC + cc, col = ch * 8 + cl;
            int w = col / W, i = col - w * W;
            d[cc] = xsrc[(size_t)(w * S + i) * M + m0 + row];
        }
    };
    auto storeA = [&](int ch) {
#pragma unroll
        for (int cc = 0; cc < PC; ++cc) {
            int cl = cg * PC + cc, col = ch * 8 + cl;
            int w = col / W, i = col - w * W;
            float ham = 0.54f - 0.46f * cosf(6.2831853071795864f * (float)i / (float)(W - 1));
            float xf = (LAYER == 2) ? __uint_as_float(xv[cc]) : fmono_inv(xv[cc]);
            float a = xf * ham;
            float s, c; __sincosf(a, &s, &c);
            float ck = c, sk = s;
#pragma unroll
            for (int k = 0; k < 5; ++k) {
                if (k > 0) { float cn = ck * c - sk * s, sn = sk * c + ck * s; ck = cn; sk = sn; }
                __half chh = __float2half_rn(ck);
                __half shh = __float2half_rn(sk);
                int kpos = cl * 10 + 2 * k;
                int frag = kpos >> 4, k16 = kpos & 15;
                int u = 2 * ((k16 & 7) >> 1) + (k16 >> 3);
                int wi_ = row * 40 + frag * 8 + (u ^ gprod);
                sAh_w[wi_] = pack_h2(ck, sk);
                sAl_w[wi_] = pack_h2(ck - __half2float(chh), sk - __half2float(shh));
            }
        }
    };
    auto cpB = [&](int ch, int b) {
        int nrow = tid >> 1, half = tid & 1;
        const __half* src = Bg + (size_t)(n0 + nrow) * KTOT + ch * 80 + half * 40;
        uint32_t dst = smem_b + 2 * ABY + (uint32_t)b * BBY + (uint32_t)nrow * 160 + half * 80;
#pragma unroll
        for (int q = 0; q < 5; ++q) cp16(dst + q * 16, src + q * 8);
        CP_COMMIT();
    };

    ldx(0, xv);
    cpB(0, 0);
    for (int ch = 0; ch < NCH; ++ch) {
        __syncthreads();                       // all warps done reading A(ch-1)
        storeA(ch);
        if (ch + 1 < NCH) ldx(ch + 1, xn);
        CP_WAIT0();
        __syncthreads();
        if (ch + 1 < NCH) cpB(ch + 1, (ch + 1) & 1);
        const uint32_t* sBw = (const uint32_t*)(dynsm + 2 * ABY + (uint32_t)(ch & 1) * BBY);

#pragma unroll
        for (int ks = 0; ks < 5; ++ks) {
            int ko = ks * 8;
            uint32_t ah[2][4], al[2][4];
#pragma unroll
            for (int m = 0; m < 2; ++m) {
                uint2 h0 = *(const uint2*)&sAh_w[aw[m][0] + ko];
                uint2 h1 = *(const uint2*)&sAh_w[aw[m][1] + ko];
                uint2 l0 = *(const uint2*)&sAl_w[aw[m][0] + ko];
                uint2 l1 = *(const uint2*)&sAl_w[aw[m][1] + ko];
                ah[m][0] = h0.x; ah[m][2] = h0.y; ah[m][1] = h1.x; ah[m][3] = h1.y;
                al[m][0] = l0.x; al[m][2] = l0.y; al[m][1] = l1.x; al[m][3] = l1.y;
            }
#pragma unroll
            for (int nn = 0; nn < 8; ++nn) {
                uint2 bb = *(const uint2*)&sBw[bw[nn] + ko];
#pragma unroll
                for (int m = 0; m < 2; ++m) {
                    mma_f16(acc[m][nn], ah[m], bb.x, bb.y);
                    mma_f16(acc[m][nn], al[m], bb.x, bb.y);
                }
            }
        }
#pragma unroll
        for (int cc = 0; cc < PC; ++cc) xv[cc] = xn[cc];
    }
    __syncthreads();   // all MMA done; smem reusable

    if constexpr (LAYER == 2) {
        // fused K-neighbor max epilogue
        float* ep = (float*)dynsm;             // [128 rows][132]
#pragma unroll
        for (int m = 0; m < 2; ++m) {
            int r0 = wm * 32 + m * 16 + qr;
#pragma unroll
            for (int nn = 0; nn < 8; ++nn) {
                int c0 = wn * 64 + nn * 8 + qk * 2;
                float bv0 = bias[n0 + c0], bv1 = bias[n0 + c0 + 1];
                ep[r0 * 132 + c0]           = acc[m][nn][0] + bv0;
                ep[r0 * 132 + c0 + 1]       = acc[m][nn][1] + bv1;
                ep[(r0 + 8) * 132 + c0]     = acc[m][nn][2] + bv0;
                ep[(r0 + 8) * 132 + c0 + 1] = acc[m][nn][3] + bv1;
            }
        }
        __syncthreads();
        int Pstart = m0 / KNN;
        int Pend = (m0 + 127) / KNN;
        int npts = Pend - Pstart + 1;          // <= 8
        for (int e2 = tid; e2 < npts * 128; e2 += 256) {
            int lp = e2 >> 7, c = e2 & 127;
            int P = Pstart + lp;
            int r0 = max(P * KNN - m0, 0);
            int r1 = min(P * KNN + KNN - m0, 128);
            float mx = -3.4e38f;
            for (int r = r0; r < r1; ++r) mx = fmaxf(mx, ep[r * 132 + c]);
            atomicMax(&g_x1m[(size_t)c * NPTS + P], fmono(mx));
        }
    } else {
        // fused global max + sum pooling (x3 never materialized)
        int batch = blockIdx.x >> 3;
#pragma unroll
        for (int nn = 0; nn < 8; ++nn) {
#pragma unroll
            for (int e = 0; e < 2; ++e) {
                int c = n0 + wn * 64 + nn * 8 + qk * 2 + e;
                float bv = bias[c];
                float v0 = acc[0][nn][e] + bv,     v1 = acc[0][nn][2 + e] + bv;
                float v2 = acc[1][nn][e] + bv,     v3 = acc[1][nn][2 + e] + bv;
                float pm = fmaxf(fmaxf(v0, v1), fmaxf(v2, v3));
                float ps = (v0 + v1) + (v2 + v3);
#pragma unroll
                for (int off = 16; off >= 4; off >>= 1) {
                    pm = fmaxf(pm, __shfl_down_sync(0xffffffffu, pm, off));
                    ps += __shfl_down_sync(0xffffffffu, ps, off);
                }
                if (lane < 4) {                  // lane == qk here
                    atomicMax(&g_xgM[batch * 1024 + c], fmono(pm));
                    atomicAdd(&g_xgS[batch * 1024 + c], ps);
                }
            }
        }
    }
}

// ---------------- layer4 ----------------
__global__ void layer4_part() {
    __shared__ float xs[2048];
    __shared__ float wsum[8][40];
    int b = blockIdx.x, sl = blockIdx.y, tid = threadIdx.x;
    for (int i = tid; i < 2048; i += 256) {
        xs[i] = (i < 1024) ? fmono_inv(g_xgM[b * 1024 + i])
                           : g_xgS[b * 1024 + i - 1024] * (1.0f / 1024.0f);
    }
    __syncthreads();
    float acc[40];
#pragma unroll
    for (int o = 0; o < 40; ++o) acc[o] = 0.f;
    for (int pp = tid; pp < 480; pp += 256) {
        int p = sl * 480 + pp;
        int w = p >> 8, i = p & 255;
        int d = (w << 7) + i;
        float ham = 0.54f - 0.46f * cosf(6.2831853071795864f * (float)i / 255.0f);
        float a = xs[d] * ham;
        float s, c; __sincosf(a, &s, &c);
        float ck = c, sk = s;
        const float* bp = g_Bp4 + (size_t)p * 400;
#pragma unroll
        for (int k = 0; k < 5; ++k) {
            if (k > 0) { float cn = ck * c - sk * s, sn = sk * c + ck * s; ck = cn; sk = sn; }
            const float* c0 = bp + (2 * k) * 40;
            const float* s0 = bp + (2 * k + 1) * 40;
#pragma unroll
            for (int o = 0; o < 40; ++o) acc[o] += ck * c0[o] + sk * s0[o];
        }
    }
    int lane = tid & 31, wp = tid >> 5;
#pragma unroll
    for (int o = 0; o < 40; ++o) {
        float t = acc[o];
#pragma unroll
        for (int off = 16; off > 0; off >>= 1) t += __shfl_down_sync(0xffffffffu, t, off);
        if (lane == 0) wsum[wp][o] = t;
    }
    __syncthreads();
    if (tid < 40) {
        float t = 0.f;
#pragma unroll
        for (int w8 = 0; w8 < 8; ++w8) t += wsum[w8][tid];
        g_l4p[(b * 8 + sl) * 40 + tid] = t;
    }
}

__global__ void layer4_final(const float* __restrict__ b4, float* __restrict__ out) {
    int t = threadIdx.x;
    if (t < 320) {
        int o = t % 40;
        int b = t / 40;
        float s = b4[o];
#pragma unroll
        for (int sl = 0; sl < 8; ++sl) s += g_l4p[(b * 8 + sl) * 40 + o];
        out[t] = s;
    }
}

// ---------------- launch ----------------
extern "C" void kernel_launch(void* const* d_in, const int* in_sizes, int n_in,
                              void* d_out, int out_size) {
    (void)in_sizes; (void)n_in; (void)out_size;
    const float* pos = (const float*)d_in[0];
    const float* c1  = (const float*)d_in[2];
    const float* b1  = (const float*)d_in[3];
    const float* c2  = (const float*)d_in[4];
    const float* b2  = (const float*)d_in[5];
    const float* c3  = (const float*)d_in[6];
    const float* b3  = (const float*)d_in[7];
    const float* c4  = (const float*)d_in[8];
    const float* b4  = (const float*)d_in[9];
    float* out = (float*)d_out;

    const int SM_L1 = 80128;                       // layer1_mma
    const int SM_K2 = 2 * 20480 + 2 * 20480;       // 81920
    const int SM_K3 = 2 * 20480 + 2 * 40960;       // 122880
    cudaFuncSetAttribute(layer1_mma, cudaFuncAttributeMaxDynamicSharedMemorySize, SM_L1);
    cudaFuncSetAttribute(kan_mma<2>, cudaFuncAttributeMaxDynamicSharedMemorySize, SM_K2);
    cudaFuncSetAttribute(kan_mma<3>, cudaFuncAttributeMaxDynamicSharedMemorySize, SM_K3);

    knn_kernel<<<32, 256>>>(pos);                                   // 0
    pack12<<<4682, 256>>>(c1, c2);                                  // 1
    layer1_mma<<<NEDGE / 128, 256, SM_L1>>>(pos, b1);               // 2
    kan_mma<2><<<dim3(NEDGE / 128, 1), 256, SM_K2>>>(b2);           // 3  <- ncu slot
    pack3<<<9024, 256>>>(c3);                                       // 4 (+xg inits)
    kan_mma<3><<<dim3(NPTS / 128, 4), 512, SM_K3>>>(b3);            // 5
    pack_coef4<<<6000, 256>>>(c4);                                  // 6
    layer4_part<<<dim3(NB, 8), 256>>>();                            // 7
    layer4_final<<<1, 320>>>(b4, out);                              // 8
}

// round 16
// speedup vs baseline: 1.1073x; 1.1073x over previous
#include <cuda_runtime.h>
#include <cuda_fp16.h>
#include <cstdint>

#define NB    8
#define PPC   1024
#define NPTS  8192
#define KNN   20
#define NEDGE (NPTS*KNN)

// ---------------- scratch (device globals; allocation-free) ----------------
__device__ int   g_nbr[NEDGE];
__device__ __align__(16) float g_h1T[64*NEDGE];    // layer1 out, TRANSPOSED [c][edge]
__device__ __align__(16) unsigned g_x1m[128*NPTS]; // max-aggregated, mono-encoded [c][n]
__device__ __align__(16) unsigned g_xgM[NB*1024];  // pooled max (mono)
__device__ __align__(16) float    g_xgS[NB*1024];  // pooled sum
__device__ __align__(16) float g_Bp4[38400*40];    // layer4 coeffs [f][o]
__device__ __align__(16) __half g_B1h[64*104];     // layer1 coeffs hi
__device__ __align__(16) __half g_B1l[64*104];     // lo
__device__ __align__(16) __half g_B2[128*1120];    // layer2 coeffs [o][f] fp16
__device__ __align__(16) __half g_B3[1024*2240];   // layer3 coeffs [o][f] fp16
__device__ float g_l4p[NB*8*40];

// ---------------- small helpers ----------------
__device__ __forceinline__ uint32_t pack_h2(float lo, float hi) {
    __half2 h = __floats2half2_rn(lo, hi);
    return *(uint32_t*)&h;
}
__device__ __forceinline__ void mma_f16(float* c, const uint32_t* a,
                                        uint32_t b0, uint32_t b1) {
    asm volatile(
        "mma.sync.aligned.m16n8k16.row.col.f32.f16.f16.f32 "
        "{%0,%1,%2,%3}, {%4,%5,%6,%7}, {%8,%9}, {%0,%1,%2,%3};\n"
        : "+f"(c[0]), "+f"(c[1]), "+f"(c[2]), "+f"(c[3])
        : "r"(a[0]), "r"(a[1]), "r"(a[2]), "r"(a[3]), "r"(b0), "r"(b1));
}
__device__ __forceinline__ void cp16(uint32_t dst, const void* src) {
    asm volatile("cp.async.cg.shared.global [%0], [%1], 16;" :: "r"(dst), "l"(src));
}
#define CP_COMMIT() asm volatile("cp.async.commit_group;" ::: "memory")
#define CP_WAIT0()  asm volatile("cp.async.wait_group 0;" ::: "memory")

// monotonic float <-> uint mapping (order-preserving under unsigned compare)
__device__ __forceinline__ unsigned fmono(float x) {
    unsigned u = __float_as_uint(x);
    return ((int)u >= 0) ? (u | 0x80000000u) : ~u;
}
__device__ __forceinline__ float fmono_inv(unsigned m) {
    return (m & 0x80000000u) ? __uint_as_float(m & 0x7fffffffu)
                             : __uint_as_float(~m);
}
#define MONO_NEG_INF 0x007fffffu

// ---------------- packing kernels ----------------
// pack12: layer1 B (hi/lo) + layer2 B (fp16 [o][f]) + init g_x1m
__global__ void pack12(const float* __restrict__ c1, const float* __restrict__ c2) {
    int idx = blockIdx.x * 256 + threadIdx.x;
    if (idx < 64 * 104) {
        int o = idx / 104, jj = idx - o * 104;
        float v = 0.f;
        if (jj < 96) {
            int c = jj >> 4, j = jj & 15;
            if (j < 10) {
                int trig = j & 1, k = j >> 1, w = c / 3, i = c % 3;
                v = c1[(((trig * 64 + o) * 2 + w) * 3 + i) * 5 + k];
            }
        }
        __half h = __float2half_rn(v);
        g_B1h[idx] = h;
        g_B1l[idx] = __float2half_rn(v - __half2float(h));
    } else if (idx < 64 * 104 + 128 * 1120) {
        int id2 = idx - 64 * 104;
        // source-major for coalesced reads
        int k = id2 % 5, r1 = id2 / 5;
        int i = r1 % 16, r2 = r1 / 16;
        int w = r2 % 7, r3 = r2 / 7;
        int o = r3 % 128, trig = r3 / 128;
        int f = ((w * 16 + i) * 5 + k) * 2 + trig;
        g_B2[o * 1120 + f] = __float2half_rn(c2[id2]);
    } else {
        int id3 = idx - (64 * 104 + 128 * 1120);
        if (id3 < 128 * NPTS) g_x1m[id3] = MONO_NEG_INF;
    }
}

// pack3: layer3 B ([o][f]) + init pooled accumulators
__global__ void pack3(const float* __restrict__ c3) {
    int idx = blockIdx.x * 256 + threadIdx.x;
    if (idx < 1024 * 2240) {
        int k = idx % 5, r1 = idx / 5;
        int i = r1 % 32, r2 = r1 / 32;
        int w = r2 % 7, r3 = r2 / 7;
        int o = r3 % 1024, trig = r3 / 1024;
        int f = ((w * 32 + i) * 5 + k) * 2 + trig;
        g_B3[(size_t)o * 2240 + f] = __float2half_rn(c3[idx]);
    } else {
        int j = idx - 1024 * 2240;
        if (j < NB * 1024) g_xgM[j] = MONO_NEG_INF;
        else if (j < 2 * NB * 1024) g_xgS[j - NB * 1024] = 0.f;
    }
}

__global__ void pack_coef4(const float* __restrict__ src) {
    int idx = blockIdx.x * 256 + threadIdx.x;
    if (idx >= 38400 * 40) return;
    int k = idx % 5, r1 = idx / 5;
    int i = r1 % 256, r2 = r1 / 256;
    int w = r2 % 15, r3 = r2 / 15;
    int o = r3 % 40, trig = r3 / 40;
    int f = ((w * 256 + i) * 5 + k) * 2 + trig;
    g_Bp4[(size_t)f * 40 + o] = src[idx];
}

// ---------------- kNN: register top-20 per query thread ----------------
__global__ void knn_kernel(const float* __restrict__ pos) {
    __shared__ float sx[PPC], sy[PPC], sz[PPC];
    int tid = threadIdx.x;
    int b   = blockIdx.x >> 2;
    int ql  = ((blockIdx.x & 3) << 8) + tid;
    for (int p = tid; p < PPC; p += 256) {
        const float* pp = pos + (b * PPC + p) * 3;
        sx[p] = pp[0]; sy[p] = pp[1]; sz[p] = pp[2];
    }
    __syncthreads();
    float qx = sx[ql], qy = sy[ql], qz = sz[ql];
    float v[KNN]; int id[KNN];
#pragma unroll
    for (int j = 0; j < KNN; ++j) { v[j] = 1e30f; id[j] = -1; }
    float vmax = 1e30f; int mpos = 0;
    for (int p = 0; p < PPC; ++p) {
        float dx = sx[p] - qx, dy = sy[p] - qy, dz = sz[p] - qz;
        float d = dx * dx + dy * dy + dz * dz;
        if (p == ql) d = 1e30f;
        if (d < vmax) {
#pragma unroll
            for (int j = 0; j < KNN; ++j) if (j == mpos) { v[j] = d; id[j] = p; }
            vmax = v[0]; mpos = 0;
#pragma unroll
            for (int j = 1; j < KNN; ++j) if (v[j] > vmax) { vmax = v[j]; mpos = j; }
        }
    }
    int q = b * PPC + ql;
#pragma unroll
    for (int j = 0; j < KNN; ++j) g_nbr[q * KNN + j] = b * PPC + id[j];
}

// ---------------- layer1 as fused-basis HMMA (fp16x3), M=128/block -----------
__global__ void __launch_bounds__(256, 2)
layer1_mma(const float* __restrict__ pos, const float* __restrict__ b1) {
    constexpr int SA1 = 104;
    extern __shared__ unsigned char smem[];
    __half* sAh = (__half*)smem;
    __half* sAl = (__half*)(smem + 26624);
    __half* sBh = (__half*)(smem + 53248);
    __half* sBl = (__half*)(smem + 66560);
    float*  bs  = (float*)(smem + 79872);
    float*  tr  = (float*)smem;

    int tid = threadIdx.x, lane = tid & 31, warp = tid >> 5;
    int wm = warp & 3, wn = warp >> 2;
    int qr = lane >> 2, qk = lane & 3;
    int row = tid & 127, cg = tid >> 7;

    if (tid >= 128) {
        int tt = tid - 128, str = tt >> 6, r = tt & 63;
        const uint4* src = (const uint4*)((str ? g_B1l : g_B1h) + r * 104);
        uint4* dst = (uint4*)((str ? sBl : sBh) + r * 104);
#pragma unroll
        for (int q = 0; q < 13; ++q) dst[q] = src[q];
    }
    if (tid < 64) bs[tid] = b1[tid];

    int edge = blockIdx.x * 128 + row;
    int n = edge / KNN;
    int pj = g_nbr[edge];
    float e[6];
    {
        const float* Pi = pos + n * 3;
        const float* Pj = pos + pj * 3;
        e[0] = Pi[0]; e[1] = Pi[1]; e[2] = Pi[2];
        e[3] = Pj[0] - Pi[0]; e[4] = Pj[1] - Pi[1]; e[5] = Pj[2] - Pi[2];
    }
#pragma unroll
    for (int cc = 0; cc < 3; ++cc) {
        int cl = cg * 3 + cc;
        int i = cl % 3;
        float ham = (i == 1) ? 1.0f : 0.08f;
        float a = e[cl] * ham;
        float s, c; __sincosf(a, &s, &c);
        uint32_t* ph = (uint32_t*)&sAh[row * SA1 + cl * 16];
        uint32_t* pl = (uint32_t*)&sAl[row * SA1 + cl * 16];
        float ck = c, sk = s;
#pragma unroll
        for (int k = 0; k < 5; ++k) {
            if (k) { float cn = ck * c - sk * s, sn = sk * c + ck * s; ck = cn; sk = sn; }
            __half chh = __float2half_rn(ck), shh = __float2half_rn(sk);
            ph[k] = pack_h2(ck, sk);
            pl[k] = pack_h2(ck - __half2float(chh), sk - __half2float(shh));
        }
        ph[5] = ph[6] = ph[7] = 0u;
        pl[5] = pl[6] = pl[7] = 0u;
    }
    __syncthreads();

    float acc[2][4][4];
#pragma unroll
    for (int m = 0; m < 2; ++m)
#pragma unroll
        for (int nf = 0; nf < 4; ++nf)
#pragma unroll
            for (int q = 0; q < 4; ++q) acc[m][nf][q] = 0.f;

#pragma unroll
    for (int ks = 0; ks < 6; ++ks) {
        int kb = ks * 16;
        uint32_t ah[2][4], al[2][4];
#pragma unroll
        for (int m = 0; m < 2; ++m) {
            int rb = (wm * 32 + m * 16 + qr) * SA1 + kb + qk * 2;
            ah[m][0] = *(const uint32_t*)&sAh[rb];
            ah[m][1] = *(const uint32_t*)&sAh[rb + 8 * SA1];
            ah[m][2] = *(const uint32_t*)&sAh[rb + 8];
            ah[m][3] = *(const uint32_t*)&sAh[rb + 8 * SA1 + 8];
            al[m][0] = *(const uint32_t*)&sAl[rb];
            al[m][1] = *(const uint32_t*)&sAl[rb + 8 * SA1];
            al[m][2] = *(const uint32_t*)&sAl[rb + 8];
            al[m][3] = *(const uint32_t*)&sAl[rb + 8 * SA1 + 8];
        }
#pragma unroll
        for (int nf = 0; nf < 4; ++nf) {
            int bb = (wn * 32 + nf * 8 + qr) * SA1 + kb + qk * 2;
            uint32_t bh0 = *(const uint32_t*)&sBh[bb];
            uint32_t bh1 = *(const uint32_t*)&sBh[bb + 8];
            uint32_t bl0 = *(const uint32_t*)&sBl[bb];
            uint32_t bl1 = *(const uint32_t*)&sBl[bb + 8];
#pragma unroll
            for (int m = 0; m < 2; ++m) {
                mma_f16(acc[m][nf], ah[m], bh0, bh1);
                mma_f16(acc[m][nf], al[m], bh0, bh1);
                mma_f16(acc[m][nf], ah[m], bl0, bl1);
            }
        }
    }
    __syncthreads();

#pragma unroll
    for (int m = 0; m < 2; ++m) {
        int r0 = wm * 32 + m * 16 + qr;
#pragma unroll
        for (int nf = 0; nf < 4; ++nf) {
            int c0 = wn * 32 + nf * 8 + qk * 2;
            tr[c0 * 132 + r0]           = acc[m][nf][0];
            tr[(c0 + 1) * 132 + r0]     = acc[m][nf][1];
            tr[c0 * 132 + r0 + 8]       = acc[m][nf][2];
            tr[(c0 + 1) * 132 + r0 + 8] = acc[m][nf][3];
        }
    }
    __syncthreads();
    int e0 = blockIdx.x * 128;
    for (int idx = tid; idx < 64 * 128; idx += 256) {
        int o = idx >> 7, r = idx & 127;
        g_h1T[(size_t)o * NEDGE + e0 + r] = tr[o * 132 + r] + bs[o];
    }
}

// ---------------- fp16x2 fused-basis GEMM, pipelined (R14 loop) -------------
// LAYER==2: 256 thr, tile 128x128; fused K-neighbor max epilogue
// LAYER==3: 512 thr, tile 128x256; fused global max+mean pooling epilogue
template<int LAYER>
__global__ void __launch_bounds__((LAYER == 2) ? 256 : 512, (LAYER == 2) ? 2 : 1)
kan_mma(const float* __restrict__ bias) {
    constexpr int W    = (LAYER == 2) ? 16 : 32;
    constexpr int S    = (LAYER == 2) ? 8  : 16;
    constexpr int M    = (LAYER == 2) ? NEDGE : NPTS;
    constexpr int NCH  = (LAYER == 2) ? 14 : 28;
    constexpr int KTOT = (LAYER == 2) ? 1120 : 2240;
    constexpr int NT   = (LAYER == 2) ? 128 : 256;   // n-cols per block
    constexpr int PC   = (LAYER == 2) ? 4 : 2;       // producer cols/thread
    constexpr int SA   = 88;                          // padded k-stride (fp16)
    constexpr uint32_t ABY = 128u * SA * 2;           // 22528
    constexpr uint32_t BBY = (uint32_t)NT * SA * 2;   // 22528 / 45056

    extern __shared__ unsigned char dynsm[];
    __half* sAh = (__half*)dynsm;
    __half* sAl = (__half*)(dynsm + ABY);
    uint32_t smem_b = (uint32_t)__cvta_generic_to_shared(dynsm);

    const unsigned* xsrc = (LAYER == 2) ? (const unsigned*)g_h1T : g_x1m;
    const __half* Bg = (LAYER == 2) ? g_B2 : g_B3;

    int m0 = blockIdx.x * 128;
    int n0 = blockIdx.y * NT;
    int tid = threadIdx.x;
    int lane = tid & 31, warp = tid >> 5;
    int wm = warp & 3, wn = warp >> 2;   // warp tile: 32 rows x 64 cols
    int qr = lane >> 2, qk = lane & 3;
    int row = tid & 127, cg = tid >> 7;  // producer mapping

    float acc[2][8][4];
#pragma unroll
    for (int m = 0; m < 2; ++m)
#pragma unroll
        for (int nn = 0; nn < 8; ++nn)
#pragma unroll
            for (int q = 0; q < 4; ++q) acc[m][nn][q] = 0.f;

    unsigned xv[PC], xn[PC];

    auto ldx = [&](int ch, unsigned* d) {
#pragma unroll
        for (int cc = 0; cc < PC; ++cc) {
            int cl = cg * PC + cc, col = ch * 8 + cl;
            int w = col / W, i = col - w * W;
            d[cc] = xsrc[(size_t)(w * S + i) * M + m0 + row];
        }
    };
    auto storeA = [&](int ch) {
#pragma unroll
        for (int cc = 0; cc < PC; ++cc) {
            int cl = cg * PC + cc, col = ch * 8 + cl;
            int w = col / W, i = col - w * W;
            float ham = 0.54f - 0.46f * cosf(6.2831853071795864f * (float)i / (float)(W - 1));
            float xf = (LAYER == 2) ? __uint_as_float(xv[cc]) : fmono_inv(xv[cc]);
            float a = xf * ham;
            float s, c; __sincosf(a, &s, &c);
            float ck = c, sk = s;
            uint32_t* ph = (uint32_t*)&sAh[row * SA + cl * 10];
            uint32_t* pl = (uint32_t*)&sAl[row * SA + cl * 10];
#pragma unroll
            for (int k = 0; k < 5; ++k) {
                if (k > 0) { float cn = ck * c - sk * s, sn = sk * c + ck * s; ck = cn; sk = sn; }
                __half chh = __float2half_rn(ck);
                __half shh = __float2half_rn(sk);
                ph[k] = pack_h2(ck, sk);
                pl[k] = pack_h2(ck - __half2float(chh), sk - __half2float(shh));
            }
        }
    };
    auto cpB = [&](int ch, int b) {
        // spread across all threads: 2 threads per n-row
        int nrow = tid >> 1, half = tid & 1;
        if (nrow < NT) {
            const __half* src = Bg + (size_t)(n0 + nrow) * KTOT + ch * 80 + half * 40;
            uint32_t dst = smem_b + 2 * ABY + (uint32_t)b * BBY
                         + (uint32_t)nrow * (SA * 2) + (uint32_t)half * 80;
#pragma unroll
            for (int q = 0; q < 5; ++q) cp16(dst + q * 16, src + q * 8);
        }
        CP_COMMIT();
    };

    ldx(0, xv);
    cpB(0, 0);
    for (int ch = 0; ch < NCH; ++ch) {
        __syncthreads();                       // all warps done reading A(ch-1)
        storeA(ch);                            // MUFU + STS, no LDG stall
        if (ch + 1 < NCH) ldx(ch + 1, xn);     // prefetch x for next chunk
        CP_WAIT0();                            // B(ch) landed
        __syncthreads();                       // A + B visible to all
        if (ch + 1 < NCH) cpB(ch + 1, (ch + 1) & 1);   // async during MMA
        const __half* sBh = (const __half*)(dynsm + 2 * ABY + (uint32_t)(ch & 1) * BBY);

#pragma unroll
        for (int ks = 0; ks < 5; ++ks) {
            int kb = ks * 16;
            uint32_t ah[2][4], al[2][4];
#pragma unroll
            for (int m = 0; m < 2; ++m) {
                int rb = (wm * 32 + m * 16 + qr) * SA + kb + qk * 2;
                ah[m][0] = *(const uint32_t*)&sAh[rb];
                ah[m][1] = *(const uint32_t*)&sAh[rb + 8 * SA];
                ah[m][2] = *(const uint32_t*)&sAh[rb + 8];
                ah[m][3] = *(const uint32_t*)&sAh[rb + 8 * SA + 8];
                al[m][0] = *(const uint32_t*)&sAl[rb];
                al[m][1] = *(const uint32_t*)&sAl[rb + 8 * SA];
                al[m][2] = *(const uint32_t*)&sAl[rb + 8];
                al[m][3] = *(const uint32_t*)&sAl[rb + 8 * SA + 8];
            }
#pragma unroll
            for (int nn = 0; nn < 8; ++nn) {
                int bb = (wn * 64 + nn * 8 + qr) * SA + kb + qk * 2;
                uint32_t bh0 = *(const uint32_t*)&sBh[bb];
                uint32_t bh1 = *(const uint32_t*)&sBh[bb + 8];
#pragma unroll
                for (int m = 0; m < 2; ++m) {
                    mma_f16(acc[m][nn], ah[m], bh0, bh1);
                    mma_f16(acc[m][nn], al[m], bh0, bh1);
                }
            }
        }
#pragma unroll
        for (int cc = 0; cc < PC; ++cc) xv[cc] = xn[cc];
    }
    __syncthreads();   // all MMA done; smem reusable

    if constexpr (LAYER == 2) {
        // fused K-neighbor max epilogue
        float* ep = (float*)dynsm;             // [128 rows][132]
#pragma unroll
        for (int m = 0; m < 2; ++m) {
            int r0 = wm * 32 + m * 16 + qr;
#pragma unroll
            for (int nn = 0; nn < 8; ++nn) {
                int c0 = wn * 64 + nn * 8 + qk * 2;
                float bv0 = bias[n0 + c0], bv1 = bias[n0 + c0 + 1];
                ep[r0 * 132 + c0]           = acc[m][nn][0] + bv0;
                ep[r0 * 132 + c0 + 1]       = acc[m][nn][1] + bv1;
                ep[(r0 + 8) * 132 + c0]     = acc[m][nn][2] + bv0;
                ep[(r0 + 8) * 132 + c0 + 1] = acc[m][nn][3] + bv1;
            }
        }
        __syncthreads();
        int Pstart = m0 / KNN;
        int Pend = (m0 + 127) / KNN;
        int npts = Pend - Pstart + 1;          // <= 8
        for (int e2 = tid; e2 < npts * 128; e2 += 256) {
            int lp = e2 >> 7, c = e2 & 127;
            int P = Pstart + lp;
            int r0 = max(P * KNN - m0, 0);
            int r1 = min(P * KNN + KNN - m0, 128);
            float mx = -3.4e38f;
            for (int r = r0; r < r1; ++r) mx = fmaxf(mx, ep[r * 132 + c]);
            atomicMax(&g_x1m[(size_t)c * NPTS + P], fmono(mx));
        }
    } else {
        // fused global max + sum pooling (x3 never materialized)
        int batch = blockIdx.x >> 3;
#pragma unroll
        for (int nn = 0; nn < 8; ++nn) {
#pragma unroll
            for (int e = 0; e < 2; ++e) {
                int c = n0 + wn * 64 + nn * 8 + qk * 2 + e;
                float bv = bias[c];
                float v0 = acc[0][nn][e] + bv,     v1 = acc[0][nn][2 + e] + bv;
                float v2 = acc[1][nn][e] + bv,     v3 = acc[1][nn][2 + e] + bv;
                float pm = fmaxf(fmaxf(v0, v1), fmaxf(v2, v3));
                float ps = (v0 + v1) + (v2 + v3);
#pragma unroll
                for (int off = 16; off >= 4; off >>= 1) {
                    pm = fmaxf(pm, __shfl_down_sync(0xffffffffu, pm, off));
                    ps += __shfl_down_sync(0xffffffffu, ps, off);
                }
                if (lane < 4) {                  // lane == qk here
                    atomicMax(&g_xgM[batch * 1024 + c], fmono(pm));
                    atomicAdd(&g_xgS[batch * 1024 + c], ps);
                }
            }
        }
    }
}

// ---------------- layer4 ----------------
__global__ void layer4_part() {
    __shared__ float xs[2048];
    __shared__ float wsum[8][40];
    int b = blockIdx.x, sl = blockIdx.y, tid = threadIdx.x;
    for (int i = tid; i < 2048; i += 256) {
        xs[i] = (i < 1024) ? fmono_inv(g_xgM[b * 1024 + i])
                           : g_xgS[b * 1024 + i - 1024] * (1.0f / 1024.0f);
    }
    __syncthreads();
    float acc[40];
#pragma unroll
    for (int o = 0; o < 40; ++o) acc[o] = 0.f;
    for (int pp = tid; pp < 480; pp += 256) {
        int p = sl * 480 + pp;
        int w = p >> 8, i = p & 255;
        int d = (w << 7) + i;
        float ham = 0.54f - 0.46f * cosf(6.2831853071795864f * (float)i / 255.0f);
        float a = xs[d] * ham;
        float s, c; __sincosf(a, &s, &c);
        float ck = c, sk = s;
        const float* bp = g_Bp4 + (size_t)p * 400;
#pragma unroll
        for (int k = 0; k < 5; ++k) {
            if (k > 0) { float cn = ck * c - sk * s, sn = sk * c + ck * s; ck = cn; sk = sn; }
            const float* c0 = bp + (2 * k) * 40;
            const float* s0 = bp + (2 * k + 1) * 40;
#pragma unroll
            for (int o = 0; o < 40; ++o) acc[o] += ck * c0[o] + sk * s0[o];
        }
    }
    int lane = tid & 31, wp = tid >> 5;
#pragma unroll
    for (int o = 0; o < 40; ++o) {
        float t = acc[o];
#pragma unroll
        for (int off = 16; off > 0; off >>= 1) t += __shfl_down_sync(0xffffffffu, t, off);
        if (lane == 0) wsum[wp][o] = t;
    }
    __syncthreads();
    if (tid < 40) {
        float t = 0.f;
#pragma unroll
        for (int w8 = 0; w8 < 8; ++w8) t += wsum[w8][tid];
        g_l4p[(b * 8 + sl) * 40 + tid] = t;
    }
}

__global__ void layer4_final(const float* __restrict__ b4, float* __restrict__ out) {
    int t = threadIdx.x;
    if (t < 320) {
        int o = t % 40;
        int b = t / 40;
        float s = b4[o];
#pragma unroll
        for (int sl = 0; sl < 8; ++sl) s += g_l4p[(b * 8 + sl) * 40 + o];
        out[t] = s;
    }
}

// ---------------- launch ----------------
extern "C" void kernel_launch(void* const* d_in, const int* in_sizes, int n_in,
                              void* d_out, int out_size) {
    (void)in_sizes; (void)n_in; (void)out_size;
    const float* pos = (const float*)d_in[0];
    const float* c1  = (const float*)d_in[2];
    const float* b1  = (const float*)d_in[3];
    const float* c2  = (const float*)d_in[4];
    const float* b2  = (const float*)d_in[5];
    const float* c3  = (const float*)d_in[6];
    const float* b3  = (const float*)d_in[7];
    const float* c4  = (const float*)d_in[8];
    const float* b4  = (const float*)d_in[9];
    float* out = (float*)d_out;

    const int SM_L1 = 80128;                          // layer1_mma
    const int SM_K2 = 2 * 22528 + 2 * 22528;          // 90112
    const int SM_K3 = 2 * 22528 + 2 * 45056;          // 135168
    cudaFuncSetAttribute(layer1_mma, cudaFuncAttributeMaxDynamicSharedMemorySize, SM_L1);
    cudaFuncSetAttribute(kan_mma<2>, cudaFuncAttributeMaxDynamicSharedMemorySize, SM_K2);
    cudaFuncSetAttribute(kan_mma<3>, cudaFuncAttributeMaxDynamicSharedMemorySize, SM_K3);

    knn_kernel<<<32, 256>>>(pos);                                   // 0
    pack12<<<4682, 256>>>(c1, c2);                                  // 1
    layer1_mma<<<NEDGE / 128, 256, SM_L1>>>(pos, b1);               // 2
    kan_mma<2><<<dim3(NEDGE / 128, 1), 256, SM_K2>>>(b2);           // 3  <- ncu slot
    pack3<<<9024, 256>>>(c3);                                       // 4 (+xg inits)
    kan_mma<3><<<dim3(NPTS / 128, 4), 512, SM_K3>>>(b3);            // 5
    pack_coef4<<<6000, 256>>>(c4);                                  // 6
    layer4_part<<<dim3(NB, 8), 256>>>();                            // 7
    layer4_final<<<1, 320>>>(b4, out);                              // 8
}